// round 5
// baseline (speedup 1.0000x reference)
#include <cuda_runtime.h>
#include <math.h>

#define EPSF 1e-8f
#define BATCH 16

// ---------------- scratch (device globals; no allocation allowed) ----------------
__device__ float g_dm4[2][BATCH][128 * 128];   // block-4 sums (p=0, g=1)
__device__ float g_cvh[2][BATCH][128 * 128];   // horizontal gaussian pass
__device__ float g_cvv[2][BATCH][128 * 128];   // vertical gaussian pass (smoothed)
__device__ float g_ot8[2][BATCH][64 * 64];     // block-8 sums
__device__ float g_sums[2][BATCH];             // per-batch totals
__device__ float g_dm_pb[BATCH];               // per-batch kl+l2
__device__ float g_ot_pb[BATCH];               // per-batch masked OT cost

// ---------------- helpers ----------------
__device__ __forceinline__ float block_reduce(float v, float* scratch)
{
    int tid = threadIdx.x + threadIdx.y * blockDim.x;
    unsigned m = 0xffffffffu;
#pragma unroll
    for (int o = 16; o > 0; o >>= 1) v += __shfl_down_sync(m, v, o);
    int lane = tid & 31, w = tid >> 5;
    int nw = (blockDim.x * blockDim.y + 31) >> 5;
    if (lane == 0) scratch[w] = v;
    __syncthreads();
    v = (tid < nw) ? scratch[tid] : 0.f;
    __syncthreads();
    if (w == 0) {
#pragma unroll
        for (int o = 16; o > 0; o >>= 1) v += __shfl_down_sync(m, v, o);
    }
    return v;  // valid in thread 0
}

__device__ __forceinline__ void make_gauss(float* gk, float* ginv, int tid)
{
    if (tid < 49) {
        float d = (float)tid - 24.f;
        gk[tid] = expf(-(d * d) * (1.f / 128.f));
    }
    __syncthreads();
    if (tid == 0) {
        float s = 0.f;
        for (int i = 0; i < 49; ++i) s += gk[i];
        *ginv = 1.f / s;
    }
    __syncthreads();
}

// ---------------- kernel 1: 4x4 block sums (memory bound: 32 MB read) ----------------
__global__ void __launch_bounds__(256) k_blocksum4(const float* __restrict__ pred,
                                                   const float* __restrict__ gt)
{
    int z = blockIdx.z;
    int arr = z >> 4, b = z & 15;
    const float* in = (arr ? gt : pred) + (size_t)b * 512 * 512;
    int x = blockIdx.x * blockDim.x + threadIdx.x;  // 0..127
    int y = blockIdx.y * blockDim.y + threadIdx.y;  // 0..127
    float s = 0.f;
#pragma unroll
    for (int r = 0; r < 4; ++r) {
        float4 v = *reinterpret_cast<const float4*>(in + (size_t)(4 * y + r) * 512 + 4 * x);
        s += v.x + v.y + v.z + v.w;
    }
    g_dm4[arr][b][y * 128 + x] = s;
}

// ---------------- kernel 2: 8x8 block sums (=2x2 of dm4) + per-batch totals ----------------
__global__ void __launch_bounds__(1024) k_ot8_sums()
{
    __shared__ float scratch[32];
    int arr = blockIdx.x >> 4, b = blockIdx.x & 15;
    const float* dm = g_dm4[arr][b];
    float* ot = g_ot8[arr][b];
    int tid = threadIdx.x;
    float loc = 0.f;
    for (int i = tid; i < 4096; i += 1024) {
        int y = i >> 6, x = i & 63;
        const float* p = dm + (2 * y) * 128 + 2 * x;
        float s = p[0] + p[1] + p[128] + p[129];
        ot[i] = s;
        loc += s;
    }
    float tot = block_reduce(loc, scratch);
    if (tid == 0) g_sums[arr][b] = tot;
}

// ---------------- kernel 3: horizontal 49-tap gaussian (smem staged) ----------------
__global__ void __launch_bounds__(256) k_convh()
{
    __shared__ float s[8][176];
    __shared__ float gk[49];
    __shared__ float ginv;
    int img = blockIdx.y;
    int arr = img >> 4, bb = img & 15;
    int y0 = blockIdx.x * 8;
    int tid = threadIdx.x;  // 256
    const float* in = g_dm4[arr][bb];
    float* out = g_cvh[arr][bb];
    make_gauss(gk, &ginv, tid);
    for (int i = tid; i < 8 * 176; i += 256) {
        int r = i / 176, c = i - r * 176;
        int sx = c - 24;
        (&s[0][0])[i] = (sx >= 0 && sx < 128) ? in[(y0 + r) * 128 + sx] : 0.f;
    }
    __syncthreads();
    int x = tid & 127, r0 = tid >> 7;  // handles rows r0, r0+2, r0+4, r0+6
    float a0 = 0.f, a1 = 0.f, a2 = 0.f, a3 = 0.f;
#pragma unroll
    for (int t = 0; t < 49; ++t) {
        float w = gk[t];
        a0 = fmaf(w, s[r0][x + t], a0);
        a1 = fmaf(w, s[r0 + 2][x + t], a1);
        a2 = fmaf(w, s[r0 + 4][x + t], a2);
        a3 = fmaf(w, s[r0 + 6][x + t], a3);
    }
    float gi = ginv;
    out[(y0 + r0) * 128 + x] = a0 * gi;
    out[(y0 + r0 + 2) * 128 + x] = a1 * gi;
    out[(y0 + r0 + 4) * 128 + x] = a2 * gi;
    out[(y0 + r0 + 6) * 128 + x] = a3 * gi;
}

// ---------------- kernel 4: vertical 49-tap gaussian (smem staged) ----------------
__global__ void __launch_bounds__(128) k_convv()
{
    __shared__ float s[80 * 128];
    __shared__ float gk[49];
    __shared__ float ginv;
    int img = blockIdx.y;
    int arr = img >> 4, bb = img & 15;
    int y0 = blockIdx.x * 32;
    int tid = threadIdx.x;  // 128
    const float* in = g_cvh[arr][bb];
    float* out = g_cvv[arr][bb];
    make_gauss(gk, &ginv, tid);
    for (int i = tid; i < 80 * 128; i += 128) {
        int r = i >> 7, x = i & 127;
        int sy = y0 - 24 + r;
        s[i] = (sy >= 0 && sy < 128) ? in[sy * 128 + x] : 0.f;
    }
    __syncthreads();
    float gi = ginv;
    int x = tid;
    for (int ry = 0; ry < 32; ++ry) {
        float acc = 0.f;
#pragma unroll
        for (int t = 0; t < 49; ++t) acc = fmaf(gk[t], s[(ry + t) * 128 + x], acc);
        out[(y0 + ry) * 128 + x] = acc * gi;
    }
}

// ---------------- kernel 5: DM KL + L2 per batch ----------------
__global__ void __launch_bounds__(1024) k_dmloss()
{
    __shared__ float scratch[32];
    __shared__ float sden[2];
    int b = blockIdx.x;
    int tid = threadIdx.x;
    const float* ps = g_cvv[0][b];
    const float* gs = g_cvv[1][b];
    float sp = 0.f, sg = 0.f;
    for (int i = tid; i < 16384; i += 1024) { sp += ps[i]; sg += gs[i]; }
    float tp = block_reduce(sp, scratch);
    if (tid == 0) sden[0] = tp;
    float tg = block_reduce(sg, scratch);
    if (tid == 0) sden[1] = tg;
    __syncthreads();
    float ip = 1.f / fmaxf(sden[0], EPSF);
    float ig = 1.f / fmaxf(sden[1], EPSF);
    float acc = 0.f;
    for (int i = tid; i < 16384; i += 1024) {
        float pn = ps[i] * ip, gn = gs[i] * ig;
        float kl = gn * logf((gn + EPSF) / (pn + EPSF));
        float d = pn - gn;
        acc += kl + d * d;
    }
    float tot = block_reduce(acc, scratch);
    if (tid == 0) g_dm_pb[b] = tot;
}

// ---------------- kernel 6: Sinkhorn (exact-in-f32 3x3 stencil form of K) ----------------
// Parity-split smem planes (even/odd x) -> all gathers stride-1, conflict-free.
// Plane: 66 rows (y halo) x 34 cols. E[r][c] = field[r-1][2c]; O[r][c] = field[r-1][2c-1].
__device__ __forceinline__ void conv_rows(const float* E, const float* O, int eb, float w1,
                                          float& t00, float& t01, float& t10, float& t11)
{
    float ra[4], rb[4];
#pragma unroll
    for (int r = 0; r < 4; ++r) {
        float e0 = E[eb + r * 34], e1 = E[eb + r * 34 + 1];
        float o0 = O[eb + r * 34], o1 = O[eb + r * 34 + 1];
        ra[r] = fmaf(w1, o0 + o1, e0);  // row-sum for even-x output
        rb[r] = fmaf(w1, e0 + e1, o1);  // row-sum for odd-x output
    }
    t00 = fmaf(w1, ra[0] + ra[2], ra[1]);
    t10 = fmaf(w1, ra[1] + ra[3], ra[2]);
    t01 = fmaf(w1, rb[0] + rb[2], rb[1]);
    t11 = fmaf(w1, rb[1] + rb[3], rb[2]);
}

__global__ void __launch_bounds__(1024) k_sinkhorn()
{
    __shared__ float UE[66 * 34], UO[66 * 34], VE[66 * 34], VO[66 * 34];
    __shared__ float red[32];
    int b = blockIdx.x;
    int tx = threadIdx.x, ty = threadIdx.y;
    int tid = ty * 32 + tx;

    for (int i = tid; i < 66 * 34; i += 1024) { UE[i] = 0.f; UO[i] = 0.f; VE[i] = 0.f; VO[i] = 0.f; }
    __syncthreads();

    int y0 = 2 * ty, x0 = 2 * tx;
    int eb = y0 * 34 + tx;  // plane row y0 (= field row y0-1), col tx

    // u = ones (interior only; halo stays 0)
    UE[eb + 34] = 1.f; UO[eb + 35] = 1.f;
    UE[eb + 68] = 1.f; UO[eb + 69] = 1.f;

    const float w1 = expf(-1.f / 0.1f);   // dist^2 = 1
    const float w2 = expf(-2.f / 0.1f);   // dist^2 = 2
    float asum = fmaxf(g_sums[0][b], EPSF);
    float bsum = fmaxf(g_sums[1][b], EPSF);
    const float* pa = g_ot8[0][b];
    const float* pb = g_ot8[1][b];
    int i00 = y0 * 64 + x0;
    float a00 = pa[i00] / asum, a01 = pa[i00 + 1] / asum;
    float a10 = pa[i00 + 64] / asum, a11 = pa[i00 + 65] / asum;
    float b00 = pb[i00] / bsum, b01 = pb[i00 + 1] / bsum;
    float b10 = pb[i00 + 64] / bsum, b11 = pb[i00 + 65] / bsum;

    float v00, v01, v10, v11;
    __syncthreads();

    for (int it = 0; it < 50; ++it) {
        float t00, t01, t10, t11;
        conv_rows(UE, UO, eb, w1, t00, t01, t10, t11);       // K @ u
        v00 = __fdividef(b00, t00 + EPSF);
        v01 = __fdividef(b01, t01 + EPSF);
        v10 = __fdividef(b10, t10 + EPSF);
        v11 = __fdividef(b11, t11 + EPSF);
        VE[eb + 34] = v00; VO[eb + 35] = v01;
        VE[eb + 68] = v10; VO[eb + 69] = v11;
        __syncthreads();
        conv_rows(VE, VO, eb, w1, t00, t01, t10, t11);       // K @ v
        UE[eb + 34] = __fdividef(a00, t00 + EPSF);
        UO[eb + 35] = __fdividef(a01, t01 + EPSF);
        UE[eb + 68] = __fdividef(a10, t10 + EPSF);
        UO[eb + 69] = __fdividef(a11, t11 + EPSF);
        __syncthreads();
    }

    // cost = sum_j v_j * ( w1 * sum_{d2=1} u_i  +  2*w2 * sum_{d2=2} u_i )  (diagonal C=0)
    float c = 0.f;
    {   // (y0, x0) even-x, plane row y0+1
        float s1 = UE[eb] + UE[eb + 68] + UO[eb + 34] + UO[eb + 35];
        float s2 = UO[eb] + UO[eb + 1] + UO[eb + 68] + UO[eb + 69];
        c += v00 * fmaf(w1, s1, 2.f * w2 * s2);
    }
    {   // (y0, x0+1) odd-x
        float s1 = UO[eb + 1] + UO[eb + 69] + UE[eb + 34] + UE[eb + 35];
        float s2 = UE[eb] + UE[eb + 1] + UE[eb + 68] + UE[eb + 69];
        c += v01 * fmaf(w1, s1, 2.f * w2 * s2);
    }
    {   // (y0+1, x0), plane row y0+2
        float s1 = UE[eb + 34] + UE[eb + 102] + UO[eb + 68] + UO[eb + 69];
        float s2 = UO[eb + 34] + UO[eb + 35] + UO[eb + 102] + UO[eb + 103];
        c += v10 * fmaf(w1, s1, 2.f * w2 * s2);
    }
    {   // (y0+1, x0+1)
        float s1 = UO[eb + 35] + UO[eb + 103] + UE[eb + 68] + UE[eb + 69];
        float s2 = UE[eb + 34] + UE[eb + 35] + UE[eb + 102] + UE[eb + 103];
        c += v11 * fmaf(w1, s1, 2.f * w2 * s2);
    }
    float tot = block_reduce(c, red);
    if (tid == 0) {
        bool mask = (asum > 0.5f) && (bsum > 0.5f);
        g_ot_pb[b] = mask ? tot : 0.f;
    }
}

// ---------------- kernel 7: final scalar (single writer -> deterministic) ----------------
__global__ void __launch_bounds__(32) k_final(const int* __restrict__ gt_counts,
                                              const int* __restrict__ cell_area,
                                              float* __restrict__ out)
{
    int lane = threadIdx.x;
    float cl = 0.f, dm = 0.f, ot = 0.f;
    if (lane < BATCH) {
        int craw = cell_area[0];
        // robust to int32 or float32 encoding of the scalar (both yield 1.0 here)
        float ca = (craw >= 1 && craw <= 1000000) ? (float)craw : __int_as_float(craw);
        float pc = fmaxf(g_sums[0][lane] / ca, 0.f);
        float d = fabsf(pc - (float)gt_counts[lane]);
        cl = (d < 10.f) ? (0.5f * d * d / 10.f) : (d - 5.f);
        dm = g_dm_pb[lane];
        ot = g_ot_pb[lane];
    }
#pragma unroll
    for (int o = 16; o > 0; o >>= 1) {
        cl += __shfl_down_sync(0xffffffffu, cl, o);
        dm += __shfl_down_sync(0xffffffffu, dm, o);
        ot += __shfl_down_sync(0xffffffffu, ot, o);
    }
    if (lane == 0)
        out[0] = 3.0f * (cl * (1.f / 16.f)) + 0.5f * (dm * (1.f / 16.f)) + 0.3f * (ot * (1.f / 16.f));
}

// ---------------- launch ----------------
extern "C" void kernel_launch(void* const* d_in, const int* in_sizes, int n_in,
                              void* d_out, int out_size)
{
    const float* pred = (const float*)d_in[0];
    const float* gt = (const float*)d_in[1];
    const int* counts = (const int*)d_in[2];
    const int* cell = (const int*)d_in[3];
    float* out = (float*)d_out;

    k_blocksum4<<<dim3(4, 16, 32), dim3(32, 8)>>>(pred, gt);
    k_ot8_sums<<<32, 1024>>>();
    k_convh<<<dim3(16, 32), 256>>>();
    k_convv<<<dim3(4, 32), 128>>>();
    k_dmloss<<<16, 1024>>>();
    k_sinkhorn<<<16, dim3(32, 32)>>>();
    k_final<<<1, 32>>>(counts, cell, out);
}